// round 1
// baseline (speedup 1.0000x reference)
#include <cuda_runtime.h>
#include <cuda_bf16.h>
#include <math.h>

// ---------------------------------------------------------------------------
// GMWA: 2-layer GATv2 + patch mapper
// Sizes
#define N_NODES 768
#define WAV 6360
#define HID 32
#define NH 4
#define GC 128          // H*HID
#define GC2 256         // [g_l | g_r]
#define P_PATCH 8
#define SUP 96
#define NEG 0.2f

#define SPLITS 8
#define CHUNK 800       // ceil(6360/8) rounded to mult of 16

// scratch (device globals; no allocation allowed)
__device__ float d_Gp[SPLITS * N_NODES * GC2];   // split-K partials
__device__ float d_G1[N_NODES * GC2];            // layer1 [g_l|g_r]
__device__ float d_G2[N_NODES * GC2];            // layer2 [g_l|g_r]
__device__ float d_z1[N_NODES * HID];            // elu(gat1 out)
__device__ float d_zh[N_NODES * HID];            // z_hemo

// ---------------------------------------------------------------------------
// GEMM: G = x[768,6360] @ [Wl|Wr][6360,256], split-K partials
__global__ void gemm_splitk(const float* __restrict__ A,
                            const float* __restrict__ Wl,
                            const float* __restrict__ Wr,
                            float* __restrict__ Gp) {
    __shared__ float As[16][64];
    __shared__ float Bs[16][64];
    int bm = blockIdx.x, bn = blockIdx.y, s = blockIdx.z;
    int tid = threadIdx.x;
    int tx = tid & 15, ty = tid >> 4;
    int k0 = s * CHUNK;
    int k1 = min(WAV, k0 + CHUNK);
    int m0 = bm * 64, n0 = bn * 64;
    int am = tid >> 2, aq = tid & 3;   // A loader: row am, float4 slot aq

    float acc[4][4];
#pragma unroll
    for (int r = 0; r < 4; r++)
#pragma unroll
        for (int c = 0; c < 4; c++) acc[r][c] = 0.f;

    for (int kt = k0; kt < k1; kt += 16) {
        // load A tile 64x16 (float4 along K; K chunk start is 16-aligned)
        int ka = kt + aq * 4;
        float4 av;
        if (ka + 3 < k1) {
            av = *(const float4*)(A + (size_t)(m0 + am) * WAV + ka);
        } else {
            float t0 = (ka + 0 < k1) ? A[(size_t)(m0 + am) * WAV + ka + 0] : 0.f;
            float t1 = (ka + 1 < k1) ? A[(size_t)(m0 + am) * WAV + ka + 1] : 0.f;
            float t2 = (ka + 2 < k1) ? A[(size_t)(m0 + am) * WAV + ka + 2] : 0.f;
            float t3 = (ka + 3 < k1) ? A[(size_t)(m0 + am) * WAV + ka + 3] : 0.f;
            av = make_float4(t0, t1, t2, t3);
        }
        As[aq * 4 + 0][am] = av.x;
        As[aq * 4 + 1][am] = av.y;
        As[aq * 4 + 2][am] = av.z;
        As[aq * 4 + 3][am] = av.w;

        // load B tile 16x64 from [Wl|Wr]
#pragma unroll
        for (int e = 0; e < 4; e++) {
            int idx = tid + e * 256;
            int kb = idx >> 6, nb = idx & 63;
            int kk = kt + kb;
            int gn = n0 + nb;
            float v = 0.f;
            if (kk < k1)
                v = (gn < GC) ? Wl[(size_t)kk * GC + gn]
                              : Wr[(size_t)kk * GC + (gn - GC)];
            Bs[kb][nb] = v;
        }
        __syncthreads();

#pragma unroll
        for (int k = 0; k < 16; k++) {
            float a[4], b[4];
#pragma unroll
            for (int r = 0; r < 4; r++) a[r] = As[k][ty * 4 + r];
#pragma unroll
            for (int c = 0; c < 4; c++) b[c] = Bs[k][tx * 4 + c];
#pragma unroll
            for (int r = 0; r < 4; r++)
#pragma unroll
                for (int c = 0; c < 4; c++)
                    acc[r][c] = fmaf(a[r], b[c], acc[r][c]);
        }
        __syncthreads();
    }

    float* out = Gp + (size_t)s * N_NODES * GC2;
#pragma unroll
    for (int r = 0; r < 4; r++)
#pragma unroll
        for (int c = 0; c < 4; c++)
            out[(size_t)(m0 + ty * 4 + r) * GC2 + (n0 + tx * 4 + c)] = acc[r][c];
}

__global__ void reduce_split(const float* __restrict__ Gp, float* __restrict__ G) {
    int i = blockIdx.x * 256 + threadIdx.x;   // 196608 elements
    float s = 0.f;
#pragma unroll
    for (int p = 0; p < SPLITS; p++) s += Gp[(size_t)p * (N_NODES * GC2) + i];
    G[i] = s;
}

// ---------------------------------------------------------------------------
// Attention: e -> mask -> softmax -> att (written straight to output region)
// block handles ITILE consecutive i rows; warp w computes j = w, w+8, ...
#define ITILE 2
__global__ void att_kernel(const float* __restrict__ G,
                           const int* __restrict__ adj,
                           const float* __restrict__ avec,
                           float* __restrict__ attO) {
    __shared__ float grs[ITILE][GC];
    __shared__ float ebuf[ITILE][NH][N_NODES];
    __shared__ float smax[ITILE][NH];
    __shared__ float sinv[ITILE][NH];

    int i0 = blockIdx.x * ITILE;
    int tid = threadIdx.x;
    int lane = tid & 31, w = tid >> 5;

    if (tid < ITILE * GC) {
        int it = tid >> 7, c = tid & 127;
        grs[it][c] = G[(size_t)(i0 + it) * GC2 + GC + c];
    }
    __syncthreads();

    float af = avec[lane];

    for (int j = w; j < N_NODES; j += 8) {
        float gl[NH];
#pragma unroll
        for (int h = 0; h < NH; h++)
            gl[h] = G[(size_t)j * GC2 + h * 32 + lane];
#pragma unroll
        for (int it = 0; it < ITILE; it++) {
#pragma unroll
            for (int h = 0; h < NH; h++) {
                float s = grs[it][h * 32 + lane] + gl[h];
                float l = fmaf(NEG, fminf(s, 0.f), fmaxf(s, 0.f));
                float v = l * af;
#pragma unroll
                for (int o = 16; o > 0; o >>= 1)
                    v += __shfl_xor_sync(0xffffffffu, v, o);
                if (lane == 0) {
                    int ad = adj[(size_t)(i0 + it) * N_NODES + j];
                    ebuf[it][h][j] = ad ? v : -1e30f;
                }
            }
        }
    }
    __syncthreads();

    // softmax over j: warp w -> (it, h)
    {
        int it = w >> 2, h = w & 3;
        float m = -1e30f;
        for (int j = lane; j < N_NODES; j += 32) m = fmaxf(m, ebuf[it][h][j]);
#pragma unroll
        for (int o = 16; o > 0; o >>= 1)
            m = fmaxf(m, __shfl_xor_sync(0xffffffffu, m, o));
        float ss = 0.f;
        for (int j = lane; j < N_NODES; j += 32) ss += expf(ebuf[it][h][j] - m);
#pragma unroll
        for (int o = 16; o > 0; o >>= 1)
            ss += __shfl_xor_sync(0xffffffffu, ss, o);
        if (lane == 0) { smax[it][h] = m; sinv[it][h] = 1.f / ss; }
    }
    __syncthreads();

    for (int idx = tid; idx < ITILE * N_NODES * NH; idx += 256) {
        int it = idx / (N_NODES * NH);
        int r = idx % (N_NODES * NH);
        int j = r >> 2, h = r & 3;
        float v = expf(ebuf[it][h][j] - smax[it][h]) * sinv[it][h];
        attO[(size_t)(i0 + it) * (N_NODES * NH) + r] = v;
    }
}

// ---------------------------------------------------------------------------
// res[i,h,f] = sum_j att[i,j,h] * g_r[j,h,f]; mean over h; optional elu
#define RT 3
__global__ void res_kernel(const float* __restrict__ G,
                           const float* __restrict__ attO,
                           float* __restrict__ outv, int doElu) {
    __shared__ float att[RT][N_NODES * NH];
    __shared__ float accsm[RT][GC];
    int i0 = blockIdx.x * RT;
    int tid = threadIdx.x;   // 128

    for (int idx = tid; idx < RT * N_NODES * NH; idx += 128) {
        int it = idx / (N_NODES * NH);
        int r = idx % (N_NODES * NH);
        att[it][r] = attO[(size_t)(i0 + it) * (N_NODES * NH) + r];
    }
    __syncthreads();

    int h = tid >> 5;
    float acc[RT];
#pragma unroll
    for (int it = 0; it < RT; it++) acc[it] = 0.f;

    for (int j = 0; j < N_NODES; j++) {
        float g = G[(size_t)j * GC2 + GC + tid];   // g_r[j, tid]
#pragma unroll
        for (int it = 0; it < RT; it++)
            acc[it] = fmaf(att[it][j * NH + h], g, acc[it]);
    }
#pragma unroll
    for (int it = 0; it < RT; it++) accsm[it][tid] = acc[it];
    __syncthreads();

    if (tid < RT * 32) {
        int it = tid >> 5, f = tid & 31;
        float m = 0.25f * (accsm[it][f] + accsm[it][32 + f] +
                           accsm[it][64 + f] + accsm[it][96 + f]);
        if (doElu) m = (m > 0.f) ? m : expm1f(m);
        outv[(size_t)(i0 + it) * HID + f] = m;
    }
}

// ---------------------------------------------------------------------------
// mapper: sta[t,p,e] = sum_d z[p*96+d, t] * Wm[p,d,e] + bm[p,e]
//         z_hemo[p*96+e, t] = sta[t,p,e]
__global__ void mapper_kernel(const float* __restrict__ z,
                              const float* __restrict__ Wm,
                              const float* __restrict__ bm,
                              float* __restrict__ staO,
                              float* __restrict__ zh) {
    __shared__ float ws[SUP * SUP];   // 36 KB
    int p = blockIdx.x;
    int tid = threadIdx.x;   // 256
    for (int idx = tid; idx < SUP * SUP; idx += 256)
        ws[idx] = Wm[(size_t)p * SUP * SUP + idx];
    __syncthreads();

    for (int idx = tid; idx < SUP * HID; idx += 256) {
        int t = idx & 31, e = idx >> 5;
        float s = bm[p * SUP + e];
        for (int d = 0; d < SUP; d++)
            s = fmaf(z[(size_t)(p * SUP + d) * HID + t], ws[d * SUP + e], s);
        staO[(size_t)t * N_NODES + p * SUP + e] = s;
        zh[(size_t)(p * SUP + e) * HID + t] = s;
    }
}

// ---------------------------------------------------------------------------
// small GEMM: G2 = zh[768,32] @ [Wl2|Wr2][32,256]
__global__ void gemm_small(const float* __restrict__ zh,
                           const float* __restrict__ Wl,
                           const float* __restrict__ Wr,
                           float* __restrict__ G) {
    __shared__ float zr[HID];
    int i = blockIdx.x;
    int c = threadIdx.x;   // 256
    if (c < HID) zr[c] = zh[(size_t)i * HID + c];
    __syncthreads();
    const float* W = (c < GC) ? Wl : Wr;
    int cc = c & 127;
    float s = 0.f;
#pragma unroll
    for (int k = 0; k < HID; k++) s = fmaf(zr[k], W[k * GC + cc], s);
    G[(size_t)i * GC2 + c] = s;
}

// ---------------------------------------------------------------------------
extern "C" void kernel_launch(void* const* d_in, const int* in_sizes, int n_in,
                              void* d_out, int out_size) {
    const float* x    = (const float*)d_in[0];
    const float* Wl1  = (const float*)d_in[1];
    const float* Wr1  = (const float*)d_in[2];
    const float* a1   = (const float*)d_in[3];
    const float* Wm   = (const float*)d_in[4];
    const float* bm   = (const float*)d_in[5];
    const float* Wl2  = (const float*)d_in[6];
    const float* Wr2  = (const float*)d_in[7];
    const float* a2   = (const float*)d_in[8];
    const int*   adjS = (const int*)d_in[9];
    const int*   adjT = (const int*)d_in[10];

    float* out  = (float*)d_out;                       // [768,32]
    float* attS = out + N_NODES * HID;                 // [768,768,4]
    float* attT = attS + (size_t)N_NODES * N_NODES * NH;
    float* staO = attT + (size_t)N_NODES * N_NODES * NH;   // [32,8,96]

    float *gp, *g1, *g2, *z1, *zh;
    cudaGetSymbolAddress((void**)&gp, d_Gp);
    cudaGetSymbolAddress((void**)&g1, d_G1);
    cudaGetSymbolAddress((void**)&g2, d_G2);
    cudaGetSymbolAddress((void**)&z1, d_z1);
    cudaGetSymbolAddress((void**)&zh, d_zh);

    // layer 1
    gemm_splitk<<<dim3(N_NODES / 64, GC2 / 64, SPLITS), 256>>>(x, Wl1, Wr1, gp);
    reduce_split<<<N_NODES * GC2 / 256, 256>>>(gp, g1);
    att_kernel<<<N_NODES / ITILE, 256>>>(g1, adjS, a1, attS);
    res_kernel<<<N_NODES / RT, 128>>>(g1, attS, z1, 1);

    // mapper
    mapper_kernel<<<P_PATCH, 256>>>(z1, Wm, bm, staO, zh);

    // layer 2
    gemm_small<<<N_NODES, 256>>>(zh, Wl2, Wr2, g2);
    att_kernel<<<N_NODES / ITILE, 256>>>(g2, adjT, a2, attT);
    res_kernel<<<N_NODES / RT, 128>>>(g2, attT, out, 0);
}

// round 2
// speedup vs baseline: 1.5048x; 1.5048x over previous
#include <cuda_runtime.h>
#include <cuda_bf16.h>
#include <math.h>

#define N_NODES 768
#define WAV 6360
#define HID 32
#define NH 4
#define GC 128          // H*HID
#define GC2 256         // [g_l | g_r]
#define P_PATCH 8
#define SUP 96
#define NEG 0.2f

#define GSPLITS 16
#define GCHUNK 400      // 15*400 + 360 = 6360, all chunk lens mult of 8

// device scratch (no allocation allowed)
__device__ float d_Gp[GSPLITS * N_NODES * GC2];   // split-K partials (12.6MB)
__device__ float d_G1[N_NODES * GC2];
__device__ float d_G2[N_NODES * GC2];
__device__ float d_z1[N_NODES * HID];
__device__ float d_zh[N_NODES * HID];
__device__ float d_es[NH * N_NODES * N_NODES];    // e scores, planar [h][i][j] (9.4MB)

// ---------------------------------------------------------------------------
// Big GEMM: G = x[768,6360] @ [Wl|Wr][6360,256]. Tile 128x128, micro 8x8,
// split-K 16. bn==0 -> Wl, bn==1 -> Wr.
__global__ void gemm_big(const float* __restrict__ A,
                         const float* __restrict__ Wl,
                         const float* __restrict__ Wr,
                         float* __restrict__ Gp) {
    __shared__ float As[8][132];
    __shared__ float Bs[8][128];
    int bm = blockIdx.x, bn = blockIdx.y, s = blockIdx.z;
    int tid = threadIdx.x;                 // 256
    int tx = tid & 15, ty = tid >> 4;      // 16x16
    int m0 = bm * 128;
    const float* W = bn ? Wr : Wl;

    int k0 = s * GCHUNK;
    int k1 = min(WAV, k0 + GCHUNK);

    // loaders
    int lm = tid & 127, lkq = tid >> 7;    // A: row lm, k-quad lkq
    float acc[8][8];
#pragma unroll
    for (int r = 0; r < 8; r++)
#pragma unroll
        for (int c = 0; c < 8; c++) acc[r][c] = 0.f;

    for (int kt = k0; kt < k1; kt += 8) {
        // A tile: 128 rows x 8 k
        float4 av = *(const float4*)(A + (size_t)(m0 + lm) * WAV + kt + lkq * 4);
        As[lkq * 4 + 0][lm] = av.x;
        As[lkq * 4 + 1][lm] = av.y;
        As[lkq * 4 + 2][lm] = av.z;
        As[lkq * 4 + 3][lm] = av.w;
        // B tile: 8 k x 128 n
#pragma unroll
        for (int q = 0; q < 4; q++)
            Bs[lkq * 4 + q][lm] = W[(size_t)(kt + lkq * 4 + q) * GC + lm];
        __syncthreads();

#pragma unroll
        for (int k = 0; k < 8; k++) {
            float a[8], b[8];
            float4 a0 = *(const float4*)&As[k][ty * 8];
            float4 a1 = *(const float4*)&As[k][ty * 8 + 4];
            float4 b0 = *(const float4*)&Bs[k][tx * 8];
            float4 b1 = *(const float4*)&Bs[k][tx * 8 + 4];
            a[0]=a0.x;a[1]=a0.y;a[2]=a0.z;a[3]=a0.w;a[4]=a1.x;a[5]=a1.y;a[6]=a1.z;a[7]=a1.w;
            b[0]=b0.x;b[1]=b0.y;b[2]=b0.z;b[3]=b0.w;b[4]=b1.x;b[5]=b1.y;b[6]=b1.z;b[7]=b1.w;
#pragma unroll
            for (int r = 0; r < 8; r++)
#pragma unroll
                for (int c = 0; c < 8; c++)
                    acc[r][c] = fmaf(a[r], b[c], acc[r][c]);
        }
        __syncthreads();
    }

    float* out = Gp + (size_t)s * N_NODES * GC2 + (size_t)bn * 128;
#pragma unroll
    for (int r = 0; r < 8; r++) {
        float* row = out + (size_t)(m0 + ty * 8 + r) * GC2 + tx * 8;
        *(float4*)(row)     = make_float4(acc[r][0], acc[r][1], acc[r][2], acc[r][3]);
        *(float4*)(row + 4) = make_float4(acc[r][4], acc[r][5], acc[r][6], acc[r][7]);
    }
}

__global__ void reduce_split(const float* __restrict__ Gp, float* __restrict__ G) {
    int i = blockIdx.x * 256 + threadIdx.x;
    float s = 0.f;
#pragma unroll
    for (int p = 0; p < GSPLITS; p++) s += Gp[(size_t)p * (N_NODES * GC2) + i];
    G[i] = s;
}

// ---------------------------------------------------------------------------
// e[i,j,h] = sum_f a[f]*lrelu(gr[i,h,f]+gl[j,h,f]), masked -> es[h][i][j]
// Tile 32 i x 64 j. 256 thr: tj=tid&15, ti=tid>>4. Thread: 2 i x 4 j (j=tj+16q).
__global__ void e_kernel(const float* __restrict__ G,
                         const int* __restrict__ adj,
                         const float* __restrict__ avec,
                         float* __restrict__ es) {
    __shared__ float grs[32][33];
    __shared__ float gls[64][33];
    __shared__ float asm_[32];

    int i0 = blockIdx.x * 32, j0 = blockIdx.y * 64;
    int tid = threadIdx.x;
    int tj = tid & 15, ti = tid >> 4;

    if (tid < 32) asm_[tid] = avec[tid];

    // adjacency for this thread's 2x4 block
    int adjv[2][4];
#pragma unroll
    for (int r = 0; r < 2; r++)
#pragma unroll
        for (int q = 0; q < 4; q++)
            adjv[r][q] = adj[(size_t)(i0 + ti * 2 + r) * N_NODES + j0 + tj + 16 * q];

    for (int h = 0; h < NH; h++) {
        __syncthreads();
        // load gr tile (32 x 32): 1 float4 per thread
        {
            int r = tid >> 3, fq = (tid & 7) * 4;
            float4 v = *(const float4*)(G + (size_t)(i0 + r) * GC2 + GC + h * 32 + fq);
            grs[r][fq + 0] = v.x; grs[r][fq + 1] = v.y;
            grs[r][fq + 2] = v.z; grs[r][fq + 3] = v.w;
        }
        // load gl tile (64 x 32): 2 float4 per thread
#pragma unroll
        for (int e2 = 0; e2 < 2; e2++) {
            int slot = tid + e2 * 256;
            int r = slot >> 3, fq = (slot & 7) * 4;
            float4 v = *(const float4*)(G + (size_t)(j0 + r) * GC2 + h * 32 + fq);
            gls[r][fq + 0] = v.x; gls[r][fq + 1] = v.y;
            gls[r][fq + 2] = v.z; gls[r][fq + 3] = v.w;
        }
        __syncthreads();

        float acc[2][4];
#pragma unroll
        for (int r = 0; r < 2; r++)
#pragma unroll
            for (int q = 0; q < 4; q++) acc[r][q] = 0.f;

#pragma unroll
        for (int f = 0; f < 32; f++) {
            float av = asm_[f];
            float gr0 = grs[ti * 2][f];
            float gr1 = grs[ti * 2 + 1][f];
            float gl[4];
#pragma unroll
            for (int q = 0; q < 4; q++) gl[q] = gls[tj + 16 * q][f];
#pragma unroll
            for (int q = 0; q < 4; q++) {
                float s0 = gr0 + gl[q];
                float s1 = gr1 + gl[q];
                acc[0][q] = fmaf(av, fmaxf(s0, NEG * s0), acc[0][q]);
                acc[1][q] = fmaf(av, fmaxf(s1, NEG * s1), acc[1][q]);
            }
        }

        float* ep = es + (size_t)h * N_NODES * N_NODES;
#pragma unroll
        for (int r = 0; r < 2; r++) {
            float* row = ep + (size_t)(i0 + ti * 2 + r) * N_NODES + j0;
#pragma unroll
            for (int q = 0; q < 4; q++)
                row[tj + 16 * q] = adjv[r][q] ? acc[r][q] : -1e30f;
        }
    }
}

// ---------------------------------------------------------------------------
// softmax over j per (i,h); write att[i,j,h] as float4 over h. Block per i.
__global__ void attw_kernel(const float* __restrict__ es,
                            float* __restrict__ attO) {
    __shared__ float pbuf[N_NODES * NH];   // [j][h]
    int i = blockIdx.x;
    int tid = threadIdx.x;                 // 128
    int lane = tid & 31, h = tid >> 5;

    const float* ep = es + ((size_t)h * N_NODES + i) * N_NODES;
    float ev[24];
    float m = -1e30f;
#pragma unroll
    for (int k = 0; k < 24; k++) {
        ev[k] = ep[lane + 32 * k];
        m = fmaxf(m, ev[k]);
    }
#pragma unroll
    for (int o = 16; o > 0; o >>= 1)
        m = fmaxf(m, __shfl_xor_sync(0xffffffffu, m, o));
    float ss = 0.f;
#pragma unroll
    for (int k = 0; k < 24; k++) {
        ev[k] = expf(ev[k] - m);
        ss += ev[k];
    }
#pragma unroll
    for (int o = 16; o > 0; o >>= 1)
        ss += __shfl_xor_sync(0xffffffffu, ss, o);
    float inv = 1.f / ss;
#pragma unroll
    for (int k = 0; k < 24; k++)
        pbuf[(lane + 32 * k) * NH + h] = ev[k] * inv;
    __syncthreads();

    float4* dst = (float4*)(attO + (size_t)i * N_NODES * NH);
    const float4* src = (const float4*)pbuf;
    for (int j = tid; j < N_NODES; j += 128) dst[j] = src[j];
}

// ---------------------------------------------------------------------------
// res: z[i,f] = 0.25 * sum_{j,h} att[i,j,h] * g_r[j,h,f]; optional elu
#define RT 6
__global__ void res_kernel(const float* __restrict__ G,
                           const float* __restrict__ attO,
                           float* __restrict__ outv, int doElu) {
    __shared__ float atts[RT][128 * NH];   // 12KB per chunk of 128 j
    __shared__ float accsm[RT][GC];
    int i0 = blockIdx.x * RT;
    int tid = threadIdx.x;                 // 128
    int h = tid >> 5;

    float acc[RT];
#pragma unroll
    for (int it = 0; it < RT; it++) acc[it] = 0.f;

    for (int c = 0; c < N_NODES / 128; c++) {
        __syncthreads();
#pragma unroll
        for (int it = 0; it < RT; it++) {
            float4 v = *(const float4*)(attO + (size_t)(i0 + it) * (N_NODES * NH)
                                        + c * 512 + tid * 4);
            *(float4*)&atts[it][tid * 4] = v;
        }
        __syncthreads();
#pragma unroll 4
        for (int jj = 0; jj < 128; jj++) {
            int j = c * 128 + jj;
            float g = G[(size_t)j * GC2 + GC + tid];
#pragma unroll
            for (int it = 0; it < RT; it++)
                acc[it] = fmaf(atts[it][jj * NH + h], g, acc[it]);
        }
    }
#pragma unroll
    for (int it = 0; it < RT; it++) accsm[it][tid] = acc[it];
    __syncthreads();

    // mean over heads + elu
    for (int idx = tid; idx < RT * 32; idx += 128) {
        int it = idx >> 5, f = idx & 31;
        float m = 0.25f * (accsm[it][f] + accsm[it][32 + f] +
                           accsm[it][64 + f] + accsm[it][96 + f]);
        if (doElu) m = (m > 0.f) ? m : expm1f(m);
        outv[(size_t)(i0 + it) * HID + f] = m;
    }
}

// ---------------------------------------------------------------------------
__global__ void mapper_kernel(const float* __restrict__ z,
                              const float* __restrict__ Wm,
                              const float* __restrict__ bm,
                              float* __restrict__ staO,
                              float* __restrict__ zh) {
    __shared__ float ws[SUP * SUP];   // 36 KB
    int p = blockIdx.x;
    int tid = threadIdx.x;            // 256
    for (int idx = tid; idx < SUP * SUP; idx += 256)
        ws[idx] = Wm[(size_t)p * SUP * SUP + idx];
    __syncthreads();

    for (int idx = tid; idx < SUP * HID; idx += 256) {
        int t = idx & 31, e = idx >> 5;
        float s = bm[p * SUP + e];
#pragma unroll 4
        for (int d = 0; d < SUP; d++)
            s = fmaf(z[(size_t)(p * SUP + d) * HID + t], ws[d * SUP + e], s);
        staO[(size_t)t * N_NODES + p * SUP + e] = s;
        zh[(size_t)(p * SUP + e) * HID + t] = s;
    }
}

__global__ void gemm_small(const float* __restrict__ zh,
                           const float* __restrict__ Wl,
                           const float* __restrict__ Wr,
                           float* __restrict__ G) {
    __shared__ float zr[HID];
    int i = blockIdx.x;
    int c = threadIdx.x;   // 256
    if (c < HID) zr[c] = zh[(size_t)i * HID + c];
    __syncthreads();
    const float* W = (c < GC) ? Wl : Wr;
    int cc = c & 127;
    float s = 0.f;
#pragma unroll
    for (int k = 0; k < HID; k++) s = fmaf(zr[k], W[k * GC + cc], s);
    G[(size_t)i * GC2 + c] = s;
}

// ---------------------------------------------------------------------------
extern "C" void kernel_launch(void* const* d_in, const int* in_sizes, int n_in,
                              void* d_out, int out_size) {
    const float* x    = (const float*)d_in[0];
    const float* Wl1  = (const float*)d_in[1];
    const float* Wr1  = (const float*)d_in[2];
    const float* a1   = (const float*)d_in[3];
    const float* Wm   = (const float*)d_in[4];
    const float* bm   = (const float*)d_in[5];
    const float* Wl2  = (const float*)d_in[6];
    const float* Wr2  = (const float*)d_in[7];
    const float* a2   = (const float*)d_in[8];
    const int*   adjS = (const int*)d_in[9];
    const int*   adjT = (const int*)d_in[10];

    float* out  = (float*)d_out;                           // [768,32]
    float* attS = out + N_NODES * HID;                     // [768,768,4]
    float* attT = attS + (size_t)N_NODES * N_NODES * NH;
    float* staO = attT + (size_t)N_NODES * N_NODES * NH;   // [32,768]

    float *gp, *g1, *g2, *z1, *zh, *es;
    cudaGetSymbolAddress((void**)&gp, d_Gp);
    cudaGetSymbolAddress((void**)&g1, d_G1);
    cudaGetSymbolAddress((void**)&g2, d_G2);
    cudaGetSymbolAddress((void**)&z1, d_z1);
    cudaGetSymbolAddress((void**)&zh, d_zh);
    cudaGetSymbolAddress((void**)&es, d_es);

    // layer 1
    gemm_big<<<dim3(N_NODES / 128, 2, GSPLITS), 256>>>(x, Wl1, Wr1, gp);
    reduce_split<<<N_NODES * GC2 / 256, 256>>>(gp, g1);
    e_kernel<<<dim3(N_NODES / 32, N_NODES / 64), 256>>>(g1, adjS, a1, es);
    attw_kernel<<<N_NODES, 128>>>(es, attS);
    res_kernel<<<N_NODES / RT, 128>>>(g1, attS, z1, 1);

    // mapper
    mapper_kernel<<<P_PATCH, 256>>>(z1, Wm, bm, staO, zh);

    // layer 2
    gemm_small<<<N_NODES, 256>>>(zh, Wl2, Wr2, g2);
    e_kernel<<<dim3(N_NODES / 32, N_NODES / 64), 256>>>(g2, adjT, a2, es);
    attw_kernel<<<N_NODES, 128>>>(es, attT);
    res_kernel<<<N_NODES / RT, 128>>>(g2, attT, out, 0);
}

// round 3
// speedup vs baseline: 1.5810x; 1.0506x over previous
#include <cuda_runtime.h>
#include <cuda_bf16.h>
#include <math.h>
#include <stdint.h>

#define N_NODES 768
#define WAV 6360
#define HID 32
#define NH 4
#define GC 128          // H*HID
#define GC2 256         // [g_l | g_r]
#define P_PATCH 8
#define SUP 96
#define NEG 0.2f

#define GSPLITS 16
#define GCHUNK 400      // 15*400 + 360 = 6360

// device scratch (no allocation allowed)
__device__ float d_Gp[GSPLITS * N_NODES * GC2];   // split-K partials
__device__ float d_G1[N_NODES * GC2];
__device__ float d_G2[N_NODES * GC2];
__device__ float d_z1[N_NODES * HID];
__device__ float d_zh[N_NODES * HID];
__device__ float d_es[NH * N_NODES * N_NODES];    // e scores, planar [h][i][j]

// ---------------------------------------------------------------------------
// tf32 helpers
__device__ __forceinline__ void tf32split(float v, uint32_t& h, uint32_t& l) {
    asm("cvt.rna.tf32.f32 %0, %1;" : "=r"(h) : "f"(v));
    float r = v - __uint_as_float(h);
    asm("cvt.rna.tf32.f32 %0, %1;" : "=r"(l) : "f"(r));
}

__device__ __forceinline__ void mma_tf32(float* c, const uint32_t* a, const uint32_t* b) {
    asm volatile(
        "mma.sync.aligned.m16n8k8.row.col.f32.tf32.tf32.f32 "
        "{%0,%1,%2,%3}, {%4,%5,%6,%7}, {%8,%9}, {%0,%1,%2,%3};"
        : "+f"(c[0]), "+f"(c[1]), "+f"(c[2]), "+f"(c[3])
        : "r"(a[0]), "r"(a[1]), "r"(a[2]), "r"(a[3]), "r"(b[0]), "r"(b[1]));
}

// ---------------------------------------------------------------------------
// Tensor-core GEMM: G = x[768,6360] @ [Wl|Wr][6360,256], split-precision tf32.
// Tile 64x64, split-K 16 (chunk 400). 128 threads = 4 warps (2x2 of 32x32).
#define TK 32
#define SMS 36   // smem row stride (k 32 + pad 4): bank(row*36+k)=(4r+k)%32 conflict-free
__global__ void gemm_tc(const float* __restrict__ A,
                        const float* __restrict__ Wl,
                        const float* __restrict__ Wr,
                        float* __restrict__ Gp) {
    __shared__ float Ah[64][SMS], Al[64][SMS];
    __shared__ float Bh[64][SMS], Bl[64][SMS];

    int bm = blockIdx.x, bn = blockIdx.y, s = blockIdx.z;
    int tid = threadIdx.x;
    int lane = tid & 31, w = tid >> 5;
    int wm = w >> 1, wn = w & 1;
    int gid = lane >> 2, tig = lane & 3;
    int m0 = bm * 64;

    const float* W = (bn < 2) ? Wl : Wr;
    int ncol0 = (bn & 1) * 64;

    int k0 = s * GCHUNK;
    int k1 = min(WAV, k0 + GCHUNK);

    // loader coords
    int ar = tid >> 1, ac0 = (tid & 1) * 16;       // A: row, k-base (16 k each)
    int bk = tid >> 2, bn0 = (tid & 3) * 16;       // B: k-row, n-base (16 n each)

    float acc[2][4][4];
#pragma unroll
    for (int mt = 0; mt < 2; mt++)
#pragma unroll
        for (int nt = 0; nt < 4; nt++)
#pragma unroll
            for (int c = 0; c < 4; c++) acc[mt][nt][c] = 0.f;

    for (int kt = k0; kt < k1; kt += TK) {
        __syncthreads();
        // --- stage A (64 x 32), convert fp32 -> tf32 hi/lo
#pragma unroll
        for (int q = 0; q < 4; q++) {
            int kk = ac0 + q * 4;
            int gk = kt + kk;
            const float* ap = A + (size_t)(m0 + ar) * WAV + gk;
            float4 v;
            if (gk + 3 < k1) v = *(const float4*)ap;
            else {
                v.x = (gk + 0 < k1) ? ap[0] : 0.f;
                v.y = (gk + 1 < k1) ? ap[1] : 0.f;
                v.z = (gk + 2 < k1) ? ap[2] : 0.f;
                v.w = (gk + 3 < k1) ? ap[3] : 0.f;
            }
            uint32_t h0, l0, h1, l1, h2, l2, h3, l3;
            tf32split(v.x, h0, l0); tf32split(v.y, h1, l1);
            tf32split(v.z, h2, l2); tf32split(v.w, h3, l3);
            *(float2*)&Ah[ar][kk]     = make_float2(__uint_as_float(h0), __uint_as_float(h1));
            *(float2*)&Ah[ar][kk + 2] = make_float2(__uint_as_float(h2), __uint_as_float(h3));
            *(float2*)&Al[ar][kk]     = make_float2(__uint_as_float(l0), __uint_as_float(l1));
            *(float2*)&Al[ar][kk + 2] = make_float2(__uint_as_float(l2), __uint_as_float(l3));
        }
        // --- stage B (32 x 64) transposed into [n][k]
        {
            int gk = kt + bk;
            bool kv = gk < k1;
            const float* bp = W + (size_t)gk * GC + ncol0 + bn0;
#pragma unroll
            for (int q = 0; q < 4; q++) {
                float4 v = kv ? *(const float4*)(bp + q * 4)
                              : make_float4(0.f, 0.f, 0.f, 0.f);
                int nn = bn0 + q * 4;
                uint32_t h, l;
                tf32split(v.x, h, l); Bh[nn + 0][bk] = __uint_as_float(h); Bl[nn + 0][bk] = __uint_as_float(l);
                tf32split(v.y, h, l); Bh[nn + 1][bk] = __uint_as_float(h); Bl[nn + 1][bk] = __uint_as_float(l);
                tf32split(v.z, h, l); Bh[nn + 2][bk] = __uint_as_float(h); Bl[nn + 2][bk] = __uint_as_float(l);
                tf32split(v.w, h, l); Bh[nn + 3][bk] = __uint_as_float(h); Bl[nn + 3][bk] = __uint_as_float(l);
            }
        }
        __syncthreads();

#pragma unroll
        for (int k8 = 0; k8 < 4; k8++) {
            int kb = k8 * 8;
            uint32_t afh[2][4], afl[2][4];
#pragma unroll
            for (int mt = 0; mt < 2; mt++) {
                int r0 = wm * 32 + mt * 16 + gid;
                afh[mt][0] = __float_as_uint(Ah[r0][kb + tig]);
                afh[mt][1] = __float_as_uint(Ah[r0 + 8][kb + tig]);
                afh[mt][2] = __float_as_uint(Ah[r0][kb + tig + 4]);
                afh[mt][3] = __float_as_uint(Ah[r0 + 8][kb + tig + 4]);
                afl[mt][0] = __float_as_uint(Al[r0][kb + tig]);
                afl[mt][1] = __float_as_uint(Al[r0 + 8][kb + tig]);
                afl[mt][2] = __float_as_uint(Al[r0][kb + tig + 4]);
                afl[mt][3] = __float_as_uint(Al[r0 + 8][kb + tig + 4]);
            }
            uint32_t bfh[4][2], bfl[4][2];
#pragma unroll
            for (int nt = 0; nt < 4; nt++) {
                int c0 = wn * 32 + nt * 8 + gid;
                bfh[nt][0] = __float_as_uint(Bh[c0][kb + tig]);
                bfh[nt][1] = __float_as_uint(Bh[c0][kb + tig + 4]);
                bfl[nt][0] = __float_as_uint(Bl[c0][kb + tig]);
                bfl[nt][1] = __float_as_uint(Bl[c0][kb + tig + 4]);
            }
#pragma unroll
            for (int mt = 0; mt < 2; mt++)
#pragma unroll
                for (int nt = 0; nt < 4; nt++) {
                    mma_tf32(acc[mt][nt], afh[mt], bfh[nt]);
                    mma_tf32(acc[mt][nt], afh[mt], bfl[nt]);
                    mma_tf32(acc[mt][nt], afl[mt], bfh[nt]);
                }
        }
    }

    // epilogue: write split partials
    float* out = Gp + (size_t)s * N_NODES * GC2;
    int nbase = bn * 64 + wn * 32;
#pragma unroll
    for (int mt = 0; mt < 2; mt++) {
        int r = m0 + wm * 32 + mt * 16 + gid;
#pragma unroll
        for (int nt = 0; nt < 4; nt++) {
            int c = nbase + nt * 8 + tig * 2;
            *(float2*)&out[(size_t)r * GC2 + c]       = make_float2(acc[mt][nt][0], acc[mt][nt][1]);
            *(float2*)&out[(size_t)(r + 8) * GC2 + c] = make_float2(acc[mt][nt][2], acc[mt][nt][3]);
        }
    }
}

__global__ void reduce_split(const float* __restrict__ Gp, float* __restrict__ G) {
    int i = blockIdx.x * 256 + threadIdx.x;
    float s = 0.f;
#pragma unroll
    for (int p = 0; p < GSPLITS; p++) s += Gp[(size_t)p * (N_NODES * GC2) + i];
    G[i] = s;
}

// ---------------------------------------------------------------------------
// e[i,j,h] = sum_f a[f]*lrelu(gr[i,h,f]+gl[j,h,f]), masked -> es[h][i][j]
__global__ void e_kernel(const float* __restrict__ G,
                         const int* __restrict__ adj,
                         const float* __restrict__ avec,
                         float* __restrict__ es) {
    __shared__ float grs[32][33];
    __shared__ float gls[64][33];
    __shared__ float asm_[32];

    int i0 = blockIdx.x * 32, j0 = blockIdx.y * 64;
    int tid = threadIdx.x;
    int tj = tid & 15, ti = tid >> 4;

    if (tid < 32) asm_[tid] = avec[tid];

    int adjv[2][4];
#pragma unroll
    for (int r = 0; r < 2; r++)
#pragma unroll
        for (int q = 0; q < 4; q++)
            adjv[r][q] = adj[(size_t)(i0 + ti * 2 + r) * N_NODES + j0 + tj + 16 * q];

    for (int h = 0; h < NH; h++) {
        __syncthreads();
        {
            int r = tid >> 3, fq = (tid & 7) * 4;
            float4 v = *(const float4*)(G + (size_t)(i0 + r) * GC2 + GC + h * 32 + fq);
            grs[r][fq + 0] = v.x; grs[r][fq + 1] = v.y;
            grs[r][fq + 2] = v.z; grs[r][fq + 3] = v.w;
        }
#pragma unroll
        for (int e2 = 0; e2 < 2; e2++) {
            int slot = tid + e2 * 256;
            int r = slot >> 3, fq = (slot & 7) * 4;
            float4 v = *(const float4*)(G + (size_t)(j0 + r) * GC2 + h * 32 + fq);
            gls[r][fq + 0] = v.x; gls[r][fq + 1] = v.y;
            gls[r][fq + 2] = v.z; gls[r][fq + 3] = v.w;
        }
        __syncthreads();

        float acc[2][4];
#pragma unroll
        for (int r = 0; r < 2; r++)
#pragma unroll
            for (int q = 0; q < 4; q++) acc[r][q] = 0.f;

#pragma unroll
        for (int f = 0; f < 32; f++) {
            float av = asm_[f];
            float gr0 = grs[ti * 2][f];
            float gr1 = grs[ti * 2 + 1][f];
            float gl[4];
#pragma unroll
            for (int q = 0; q < 4; q++) gl[q] = gls[tj + 16 * q][f];
#pragma unroll
            for (int q = 0; q < 4; q++) {
                float s0 = gr0 + gl[q];
                float s1 = gr1 + gl[q];
                acc[0][q] = fmaf(av, fmaxf(s0, NEG * s0), acc[0][q]);
                acc[1][q] = fmaf(av, fmaxf(s1, NEG * s1), acc[1][q]);
            }
        }

        float* ep = es + (size_t)h * N_NODES * N_NODES;
#pragma unroll
        for (int r = 0; r < 2; r++) {
            float* row = ep + (size_t)(i0 + ti * 2 + r) * N_NODES + j0;
#pragma unroll
            for (int q = 0; q < 4; q++)
                row[tj + 16 * q] = adjv[r][q] ? acc[r][q] : -1e30f;
        }
    }
}

// ---------------------------------------------------------------------------
// softmax over j per (i,h); 256 threads, 2 warps per head.
__global__ void attw_kernel(const float* __restrict__ es,
                            float* __restrict__ attO) {
    __shared__ float pbuf[N_NODES * NH];
    __shared__ float wmax[8];
    __shared__ float wsum[8];
    int i = blockIdx.x;
    int tid = threadIdx.x;                 // 256
    int lane = tid & 31, w = tid >> 5;
    int h = w >> 1, half = w & 1;

    const float* ep = es + ((size_t)h * N_NODES + i) * N_NODES + half * 384;
    float ev[12];
    float m = -1e30f;
#pragma unroll
    for (int k = 0; k < 12; k++) {
        ev[k] = ep[lane + 32 * k];
        m = fmaxf(m, ev[k]);
    }
#pragma unroll
    for (int o = 16; o > 0; o >>= 1)
        m = fmaxf(m, __shfl_xor_sync(0xffffffffu, m, o));
    if (lane == 0) wmax[w] = m;
    __syncthreads();
    float M = fmaxf(wmax[h * 2], wmax[h * 2 + 1]);

    float ss = 0.f;
#pragma unroll
    for (int k = 0; k < 12; k++) {
        ev[k] = expf(ev[k] - M);
        ss += ev[k];
    }
#pragma unroll
    for (int o = 16; o > 0; o >>= 1)
        ss += __shfl_xor_sync(0xffffffffu, ss, o);
    if (lane == 0) wsum[w] = ss;
    __syncthreads();
    float inv = 1.f / (wsum[h * 2] + wsum[h * 2 + 1]);

#pragma unroll
    for (int k = 0; k < 12; k++)
        pbuf[(half * 384 + lane + 32 * k) * NH + h] = ev[k] * inv;
    __syncthreads();

    float4* dst = (float4*)(attO + (size_t)i * N_NODES * NH);
    const float4* src = (const float4*)pbuf;
    for (int j = tid; j < N_NODES; j += 256) dst[j] = src[j];
}

// ---------------------------------------------------------------------------
// res: z[i,f] = 0.25 * sum_{j,h} att[i,j,h] * g_r[j,h,f]; optional elu
#define RT 6
__global__ void res_kernel(const float* __restrict__ G,
                           const float* __restrict__ attO,
                           float* __restrict__ outv, int doElu) {
    __shared__ float atts[RT][128 * NH];
    __shared__ float accsm[RT][GC];
    int i0 = blockIdx.x * RT;
    int tid = threadIdx.x;                 // 128
    int h = tid >> 5;

    float acc[RT];
#pragma unroll
    for (int it = 0; it < RT; it++) acc[it] = 0.f;

    for (int c = 0; c < N_NODES / 128; c++) {
        __syncthreads();
#pragma unroll
        for (int it = 0; it < RT; it++) {
            float4 v = *(const float4*)(attO + (size_t)(i0 + it) * (N_NODES * NH)
                                        + c * 512 + tid * 4);
            *(float4*)&atts[it][tid * 4] = v;
        }
        __syncthreads();
#pragma unroll 4
        for (int jj = 0; jj < 128; jj++) {
            int j = c * 128 + jj;
            float g = G[(size_t)j * GC2 + GC + tid];
#pragma unroll
            for (int it = 0; it < RT; it++)
                acc[it] = fmaf(atts[it][jj * NH + h], g, acc[it]);
        }
    }
#pragma unroll
    for (int it = 0; it < RT; it++) accsm[it][tid] = acc[it];
    __syncthreads();

    for (int idx = tid; idx < RT * 32; idx += 128) {
        int it = idx >> 5, f = idx & 31;
        float m = 0.25f * (accsm[it][f] + accsm[it][32 + f] +
                           accsm[it][64 + f] + accsm[it][96 + f]);
        if (doElu) m = (m > 0.f) ? m : expm1f(m);
        outv[(size_t)(i0 + it) * HID + f] = m;
    }
}

// ---------------------------------------------------------------------------
__global__ void mapper_kernel(const float* __restrict__ z,
                              const float* __restrict__ Wm,
                              const float* __restrict__ bm,
                              float* __restrict__ staO,
                              float* __restrict__ zh) {
    __shared__ float ws[SUP * SUP];
    int p = blockIdx.x;
    int tid = threadIdx.x;            // 256
    for (int idx = tid; idx < SUP * SUP; idx += 256)
        ws[idx] = Wm[(size_t)p * SUP * SUP + idx];
    __syncthreads();

    for (int idx = tid; idx < SUP * HID; idx += 256) {
        int t = idx & 31, e = idx >> 5;
        float s = bm[p * SUP + e];
#pragma unroll 4
        for (int d = 0; d < SUP; d++)
            s = fmaf(z[(size_t)(p * SUP + d) * HID + t], ws[d * SUP + e], s);
        staO[(size_t)t * N_NODES + p * SUP + e] = s;
        zh[(size_t)(p * SUP + e) * HID + t] = s;
    }
}

__global__ void gemm_small(const float* __restrict__ zh,
                           const float* __restrict__ Wl,
                           const float* __restrict__ Wr,
                           float* __restrict__ G) {
    __shared__ float zr[HID];
    int i = blockIdx.x;
    int c = threadIdx.x;   // 256
    if (c < HID) zr[c] = zh[(size_t)i * HID + c];
    __syncthreads();
    const float* W = (c < GC) ? Wl : Wr;
    int cc = c & 127;
    float s = 0.f;
#pragma unroll
    for (int k = 0; k < HID; k++) s = fmaf(zr[k], W[k * GC + cc], s);
    G[(size_t)i * GC2 + c] = s;
}

// ---------------------------------------------------------------------------
extern "C" void kernel_launch(void* const* d_in, const int* in_sizes, int n_in,
                              void* d_out, int out_size) {
    const float* x    = (const float*)d_in[0];
    const float* Wl1  = (const float*)d_in[1];
    const float* Wr1  = (const float*)d_in[2];
    const float* a1   = (const float*)d_in[3];
    const float* Wm   = (const float*)d_in[4];
    const float* bm   = (const float*)d_in[5];
    const float* Wl2  = (const float*)d_in[6];
    const float* Wr2  = (const float*)d_in[7];
    const float* a2   = (const float*)d_in[8];
    const int*   adjS = (const int*)d_in[9];
    const int*   adjT = (const int*)d_in[10];

    float* out  = (float*)d_out;                           // [768,32]
    float* attS = out + N_NODES * HID;                     // [768,768,4]
    float* attT = attS + (size_t)N_NODES * N_NODES * NH;
    float* staO = attT + (size_t)N_NODES * N_NODES * NH;   // [32,768]

    float *gp, *g1, *g2, *z1, *zh, *es;
    cudaGetSymbolAddress((void**)&gp, d_Gp);
    cudaGetSymbolAddress((void**)&g1, d_G1);
    cudaGetSymbolAddress((void**)&g2, d_G2);
    cudaGetSymbolAddress((void**)&z1, d_z1);
    cudaGetSymbolAddress((void**)&zh, d_zh);
    cudaGetSymbolAddress((void**)&es, d_es);

    // layer 1
    gemm_tc<<<dim3(N_NODES / 64, 4, GSPLITS), 128>>>(x, Wl1, Wr1, gp);
    reduce_split<<<N_NODES * GC2 / 256, 256>>>(gp, g1);
    e_kernel<<<dim3(N_NODES / 32, N_NODES / 64), 256>>>(g1, adjS, a1, es);
    attw_kernel<<<N_NODES, 256>>>(es, attS);
    res_kernel<<<N_NODES / RT, 128>>>(g1, attS, z1, 1);

    // mapper
    mapper_kernel<<<P_PATCH, 256>>>(z1, Wm, bm, staO, zh);

    // layer 2
    gemm_small<<<N_NODES, 256>>>(zh, Wl2, Wr2, g2);
    e_kernel<<<dim3(N_NODES / 32, N_NODES / 64), 256>>>(g2, adjT, a2, es);
    attw_kernel<<<N_NODES, 256>>>(es, attT);
    res_kernel<<<N_NODES / RT, 128>>>(g2, attT, out, 0);
}

// round 4
// speedup vs baseline: 2.2212x; 1.4049x over previous
#include <cuda_runtime.h>
#include <cuda_fp16.h>
#include <math.h>
#include <stdint.h>

#define N_NODES 768
#define WAV 6360
#define HID 32
#define NH 4
#define GC 128          // H*HID
#define GC2 256         // [g_l | g_r]
#define P_PATCH 8
#define SUP 96
#define NEG 0.2f

#define GSPLITS 12
#define CHUNK 544       // 17 stages of 32; last split zero-filled past 6360
#define NSTAGE 17

// device scratch (no allocation allowed)
__device__ float d_Gp[GSPLITS * N_NODES * GC2];
__device__ float d_G1[N_NODES * GC2];
__device__ float d_G2[N_NODES * GC2];
__device__ float d_z1[N_NODES * HID];
__device__ float d_zh[N_NODES * HID];
__device__ float d_es[NH * N_NODES * N_NODES];    // e scores [h][i][j]
__device__ __half d_Wh[WAV * GC2];                // [Wl|Wr] hi halves
__device__ __half d_Wlo[WAV * GC2];               // lo halves

// ---------------------------------------------------------------------------
// PTX helpers
__device__ __forceinline__ void ldsm_x4(uint32_t* r, uint32_t a) {
    asm volatile("ldmatrix.sync.aligned.m8n8.x4.shared.b16 {%0,%1,%2,%3}, [%4];"
                 : "=r"(r[0]), "=r"(r[1]), "=r"(r[2]), "=r"(r[3]) : "r"(a));
}
__device__ __forceinline__ void ldsm_x4t(uint32_t* r, uint32_t a) {
    asm volatile("ldmatrix.sync.aligned.m8n8.x4.trans.shared.b16 {%0,%1,%2,%3}, [%4];"
                 : "=r"(r[0]), "=r"(r[1]), "=r"(r[2]), "=r"(r[3]) : "r"(a));
}
__device__ __forceinline__ void mma_f16(float* c, const uint32_t* a, const uint32_t* b) {
    asm volatile("mma.sync.aligned.m16n8k16.row.col.f32.f16.f16.f32 "
                 "{%0,%1,%2,%3}, {%4,%5,%6,%7}, {%8,%9}, {%0,%1,%2,%3};"
                 : "+f"(c[0]), "+f"(c[1]), "+f"(c[2]), "+f"(c[3])
                 : "r"(a[0]), "r"(a[1]), "r"(a[2]), "r"(a[3]), "r"(b[0]), "r"(b[1]));
}
__device__ __forceinline__ void cpa16(uint32_t d, const void* s, int sz) {
    asm volatile("cp.async.cg.shared.global [%0], [%1], 16, %2;" :: "r"(d), "l"(s), "r"(sz));
}
__device__ __forceinline__ void cp_commit() { asm volatile("cp.async.commit_group;"); }
__device__ __forceinline__ void cp_wait1() { asm volatile("cp.async.wait_group 1;"); }
__device__ __forceinline__ void cp_wait0() { asm volatile("cp.async.wait_group 0;"); }

// ---------------------------------------------------------------------------
// W pre-split: [Wl|Wr] fp32 -> hi/lo fp16
__global__ void split_w(const float* __restrict__ Wl, const float* __restrict__ Wr,
                        __half* __restrict__ Wh, __half* __restrict__ Wlo) {
    int idx = blockIdx.x * 256 + threadIdx.x;
    if (idx >= WAV * GC2) return;
    int col = idx & 255, row = idx >> 8;
    float v = (col < GC) ? Wl[row * GC + col] : Wr[row * GC + (col - GC)];
    __half h = __float2half_rn(v);
    float r = v - __half2float(h);
    Wh[idx] = h;
    Wlo[idx] = __float2half_rn(r);
}

// ---------------------------------------------------------------------------
// fp16-split tensor-core GEMM: Gp[s] += x[64m tile, chunk] @ W[chunk, 256]
// tile 64x256, 256 thr (8 warps 2m x 4n), double-buffered cp.async B + reg-prefetch A.
#define ASTR 40                 // A smem row stride (halfs): 32 + 8 pad
#define BSTR 264                // B smem row stride (halfs): 256 + 8 pad
#define A_HALF (64 * ASTR)      // 2560 halfs per stage per half-matrix
#define B_HALF (32 * BSTR)      // 8448

__global__ __launch_bounds__(256, 1)
void gemm_tc(const float* __restrict__ X,
             const __half* __restrict__ Wh,
             const __half* __restrict__ Wlo,
             float* __restrict__ Gp) {
    extern __shared__ __half sm[];
    __half* Ah = sm;                     // [2][A_HALF]
    __half* Al = Ah + 2 * A_HALF;
    __half* Bh = Al + 2 * A_HALF;        // [2][B_HALF]
    __half* Bl = Bh + 2 * B_HALF;

    uint32_t sAh = (uint32_t)__cvta_generic_to_shared(Ah);
    uint32_t sAl = (uint32_t)__cvta_generic_to_shared(Al);
    uint32_t sBh = (uint32_t)__cvta_generic_to_shared(Bh);
    uint32_t sBl = (uint32_t)__cvta_generic_to_shared(Bl);

    int bm = blockIdx.x, s = blockIdx.y;
    int tid = threadIdx.x, lane = tid & 31, w = tid >> 5;
    int wm = w >> 2, wn = w & 3;
    int m0 = bm * 64;
    int k0 = s * CHUNK;

    int arow = tid >> 2, aq = (tid & 3) * 4;   // A loader: row, k-offsets aq / aq+16

    float acc[2][8][4];
#pragma unroll
    for (int mt = 0; mt < 2; mt++)
#pragma unroll
        for (int nt = 0; nt < 8; nt++)
#pragma unroll
            for (int c = 0; c < 4; c++) acc[mt][nt][c] = 0.f;

    float4 a0, a1;   // A prefetch regs

    auto ldgA = [&](int st) {
        int kt = k0 + st * 32;
        const float* p = X + (size_t)(m0 + arow) * WAV + kt;
        a0 = (kt + aq < WAV) ? *(const float4*)(p + aq)
                             : make_float4(0.f, 0.f, 0.f, 0.f);
        a1 = (kt + aq + 16 < WAV) ? *(const float4*)(p + aq + 16)
                                  : make_float4(0.f, 0.f, 0.f, 0.f);
    };
    auto stsA = [&](int st) {
        int base = (st & 1) * A_HALF + arow * ASTR;
#pragma unroll
        for (int half2i = 0; half2i < 2; half2i++) {
            float4 v = half2i ? a1 : a0;
            int off = base + aq + half2i * 16;
            __half hx = __float2half_rn(v.x), hy = __float2half_rn(v.y);
            __half hz = __float2half_rn(v.z), hw = __float2half_rn(v.w);
            *(__half2*)(Ah + off)     = __halves2half2(hx, hy);
            *(__half2*)(Ah + off + 2) = __halves2half2(hz, hw);
            *(__half2*)(Al + off)     = __halves2half2(
                __float2half_rn(v.x - __half2float(hx)),
                __float2half_rn(v.y - __half2float(hy)));
            *(__half2*)(Al + off + 2) = __halves2half2(
                __float2half_rn(v.z - __half2float(hz)),
                __float2half_rn(v.w - __half2float(hw)));
        }
    };
    auto cpB = [&](int st) {
        int kt = k0 + st * 32;
        int sb = (st & 1) * B_HALF;
#pragma unroll
        for (int q = 0; q < 4; q++) {
            int idx = tid + q * 256;
            int row = idx >> 5, ch = (idx & 31) * 8;
            int k = kt + row;
            int sz = (k < WAV) ? 16 : 0;
            int kc = (k < WAV) ? k : (WAV - 1);
            uint32_t doff = (uint32_t)(sb + row * BSTR + ch) * 2;
            cpa16(sBh + doff, Wh + (size_t)kc * GC2 + ch, sz);
            cpa16(sBl + doff, Wlo + (size_t)kc * GC2 + ch, sz);
        }
        cp_commit();
    };
    auto compute = [&](int b) {
        uint32_t aOffH = sAh + (uint32_t)(b * A_HALF) * 2;
        uint32_t aOffL = sAl + (uint32_t)(b * A_HALF) * 2;
        uint32_t bOffH = sBh + (uint32_t)(b * B_HALF) * 2;
        uint32_t bOffL = sBl + (uint32_t)(b * B_HALF) * 2;
        int l15 = lane & 15, lhi = (lane >> 4) << 3;
#pragma unroll
        for (int k16 = 0; k16 < 32; k16 += 16) {
            uint32_t ah[2][4], al[2][4];
#pragma unroll
            for (int mt = 0; mt < 2; mt++) {
                uint32_t off = (uint32_t)((wm * 32 + mt * 16 + l15) * ASTR + k16 + lhi) * 2;
                ldsm_x4(ah[mt], aOffH + off);
                ldsm_x4(al[mt], aOffL + off);
            }
#pragma unroll
            for (int p = 0; p < 4; p++) {
                uint32_t offb = (uint32_t)((k16 + l15) * BSTR + wn * 64 + p * 16 + lhi) * 2;
                uint32_t bh[4], bl[4];
                ldsm_x4t(bh, bOffH + offb);
                ldsm_x4t(bl, bOffL + offb);
#pragma unroll
                for (int mt = 0; mt < 2; mt++) {
                    mma_f16(acc[mt][2 * p],     ah[mt], bh);
                    mma_f16(acc[mt][2 * p],     ah[mt], bl);
                    mma_f16(acc[mt][2 * p],     al[mt], bh);
                    mma_f16(acc[mt][2 * p + 1], ah[mt], bh + 2);
                    mma_f16(acc[mt][2 * p + 1], ah[mt], bl + 2);
                    mma_f16(acc[mt][2 * p + 1], al[mt], bh + 2);
                }
            }
        }
    };

    // prologue
    ldgA(0); stsA(0); cpB(0);
    for (int it = 0; it < NSTAGE; it++) {
        if (it + 1 < NSTAGE) { ldgA(it + 1); cpB(it + 1); }
        if (it + 1 < NSTAGE) cp_wait1(); else cp_wait0();
        __syncthreads();
        compute(it & 1);
        if (it + 1 < NSTAGE) stsA(it + 1);
        __syncthreads();
    }

    // epilogue
    float* out = Gp + (size_t)s * N_NODES * GC2;
    int gid = lane >> 2, tig = lane & 3;
#pragma unroll
    for (int mt = 0; mt < 2; mt++) {
        int r = m0 + wm * 32 + mt * 16 + gid;
#pragma unroll
        for (int nt = 0; nt < 8; nt++) {
            int c = wn * 64 + nt * 8 + tig * 2;
            *(float2*)&out[(size_t)r * GC2 + c] =
                make_float2(acc[mt][nt][0], acc[mt][nt][1]);
            *(float2*)&out[(size_t)(r + 8) * GC2 + c] =
                make_float2(acc[mt][nt][2], acc[mt][nt][3]);
        }
    }
}

__global__ void reduce_split(const float* __restrict__ Gp, float* __restrict__ G) {
    int i = blockIdx.x * 256 + threadIdx.x;
    float s = 0.f;
#pragma unroll
    for (int p = 0; p < GSPLITS; p++) s += Gp[(size_t)p * (N_NODES * GC2) + i];
    G[i] = s;
}

// ---------------------------------------------------------------------------
// e[i,j,h] = sum_f a[f]*lrelu(gr[i,h,f]+gl[j,h,f]), masked -> es[h][i][j]
__global__ void e_kernel(const float* __restrict__ G,
                         const int* __restrict__ adj,
                         const float* __restrict__ avec,
                         float* __restrict__ es) {
    __shared__ float grs[32][33];
    __shared__ float gls[64][33];
    __shared__ float asm_[32];

    int i0 = blockIdx.x * 32, j0 = blockIdx.y * 64;
    int tid = threadIdx.x;
    int tj = tid & 15, ti = tid >> 4;

    if (tid < 32) asm_[tid] = avec[tid];

    int adjv[2][4];
#pragma unroll
    for (int r = 0; r < 2; r++)
#pragma unroll
        for (int q = 0; q < 4; q++)
            adjv[r][q] = adj[(size_t)(i0 + ti * 2 + r) * N_NODES + j0 + tj + 16 * q];

    for (int h = 0; h < NH; h++) {
        __syncthreads();
        {
            int r = tid >> 3, fq = (tid & 7) * 4;
            float4 v = *(const float4*)(G + (size_t)(i0 + r) * GC2 + GC + h * 32 + fq);
            grs[r][fq + 0] = v.x; grs[r][fq + 1] = v.y;
            grs[r][fq + 2] = v.z; grs[r][fq + 3] = v.w;
        }
#pragma unroll
        for (int e2 = 0; e2 < 2; e2++) {
            int slot = tid + e2 * 256;
            int r = slot >> 3, fq = (slot & 7) * 4;
            float4 v = *(const float4*)(G + (size_t)(j0 + r) * GC2 + h * 32 + fq);
            gls[r][fq + 0] = v.x; gls[r][fq + 1] = v.y;
            gls[r][fq + 2] = v.z; gls[r][fq + 3] = v.w;
        }
        __syncthreads();

        float acc[2][4];
#pragma unroll
        for (int r = 0; r < 2; r++)
#pragma unroll
            for (int q = 0; q < 4; q++) acc[r][q] = 0.f;

#pragma unroll
        for (int f = 0; f < 32; f++) {
            float av = asm_[f];
            float gr0 = grs[ti * 2][f];
            float gr1 = grs[ti * 2 + 1][f];
            float gl[4];
#pragma unroll
            for (int q = 0; q < 4; q++) gl[q] = gls[tj + 16 * q][f];
#pragma unroll
            for (int q = 0; q < 4; q++) {
                float s0 = gr0 + gl[q];
                float s1 = gr1 + gl[q];
                acc[0][q] = fmaf(av, fmaxf(s0, NEG * s0), acc[0][q]);
                acc[1][q] = fmaf(av, fmaxf(s1, NEG * s1), acc[1][q]);
            }
        }

        float* ep = es + (size_t)h * N_NODES * N_NODES;
#pragma unroll
        for (int r = 0; r < 2; r++) {
            float* row = ep + (size_t)(i0 + ti * 2 + r) * N_NODES + j0;
#pragma unroll
            for (int q = 0; q < 4; q++)
                row[tj + 16 * q] = adjv[r][q] ? acc[r][q] : -1e30f;
        }
    }
}

// ---------------------------------------------------------------------------
// softmax over j per (i,h); 256 threads, 2 warps per head.
__global__ void attw_kernel(const float* __restrict__ es,
                            float* __restrict__ attO) {
    __shared__ float pbuf[N_NODES * NH];
    __shared__ float wmax[8];
    __shared__ float wsum[8];
    int i = blockIdx.x;
    int tid = threadIdx.x;                 // 256
    int lane = tid & 31, w = tid >> 5;
    int h = w >> 1, half = w & 1;

    const float* ep = es + ((size_t)h * N_NODES + i) * N_NODES + half * 384;
    float ev[12];
    float m = -1e30f;
#pragma unroll
    for (int k = 0; k < 12; k++) {
        ev[k] = ep[lane + 32 * k];
        m = fmaxf(m, ev[k]);
    }
#pragma unroll
    for (int o = 16; o > 0; o >>= 1)
        m = fmaxf(m, __shfl_xor_sync(0xffffffffu, m, o));
    if (lane == 0) wmax[w] = m;
    __syncthreads();
    float M = fmaxf(wmax[h * 2], wmax[h * 2 + 1]);

    float ss = 0.f;
#pragma unroll
    for (int k = 0; k < 12; k++) {
        ev[k] = expf(ev[k] - M);
        ss += ev[k];
    }
#pragma unroll
    for (int o = 16; o > 0; o >>= 1)
        ss += __shfl_xor_sync(0xffffffffu, ss, o);
    if (lane == 0) wsum[w] = ss;
    __syncthreads();
    float inv = 1.f / (wsum[h * 2] + wsum[h * 2 + 1]);

#pragma unroll
    for (int k = 0; k < 12; k++)
        pbuf[(half * 384 + lane + 32 * k) * NH + h] = ev[k] * inv;
    __syncthreads();

    float4* dst = (float4*)(attO + (size_t)i * N_NODES * NH);
    const float4* src = (const float4*)pbuf;
    for (int j = tid; j < N_NODES; j += 256) dst[j] = src[j];
}

// ---------------------------------------------------------------------------
// res: z[i,f] = 0.25 * sum_{j,h} att[i,j,h] * g_r[j,h,f]; 2-way j split
#define RT 6
__global__ void res_kernel(const float* __restrict__ G,
                           const float* __restrict__ attO,
                           float* __restrict__ outv, int doElu) {
    __shared__ float atts[2][RT][512];
    __shared__ float accsm[2][RT][GC];
    int i0 = blockIdx.x * RT;
    int tid = threadIdx.x;                 // 256
    int half = tid >> 7, t = tid & 127;
    int h = t >> 5;

    float acc[RT];
#pragma unroll
    for (int it = 0; it < RT; it++) acc[it] = 0.f;

    for (int c = 0; c < 3; c++) {          // 3 chunks of 128 j per half
        __syncthreads();
#pragma unroll
        for (int it = 0; it < RT; it++) {
            float4 v = *(const float4*)(attO + (size_t)(i0 + it) * (N_NODES * NH)
                                        + half * 1536 + c * 512 + t * 4);
            *(float4*)&atts[half][it][t * 4] = v;
        }
        __syncthreads();
#pragma unroll 4
        for (int jj = 0; jj < 128; jj++) {
            int j = half * 384 + c * 128 + jj;
            float g = G[(size_t)j * GC2 + GC + t];
#pragma unroll
            for (int it = 0; it < RT; it++)
                acc[it] = fmaf(atts[half][it][jj * NH + h], g, acc[it]);
        }
    }
#pragma unroll
    for (int it = 0; it < RT; it++) accsm[half][it][t] = acc[it];
    __syncthreads();

    if (tid < RT * 32) {
        int it = tid >> 5, f = tid & 31;
        float m = 0.f;
#pragma unroll
        for (int hh = 0; hh < 2; hh++)
#pragma unroll
            for (int q = 0; q < 4; q++)
                m += accsm[hh][it][q * 32 + f];
        m *= 0.25f;
        if (doElu) m = (m > 0.f) ? m : expm1f(m);
        outv[(size_t)(i0 + it) * HID + f] = m;
    }
}

// ---------------------------------------------------------------------------
__global__ void mapper_kernel(const float* __restrict__ z,
                              const float* __restrict__ Wm,
                              const float* __restrict__ bm,
                              float* __restrict__ staO,
                              float* __restrict__ zh) {
    __shared__ float ws[SUP * SUP];
    int p = blockIdx.x;
    int tid = threadIdx.x;            // 256
    for (int idx = tid; idx < SUP * SUP; idx += 256)
        ws[idx] = Wm[(size_t)p * SUP * SUP + idx];
    __syncthreads();

    for (int idx = tid; idx < SUP * HID; idx += 256) {
        int t = idx & 31, e = idx >> 5;
        float s = bm[p * SUP + e];
#pragma unroll 4
        for (int d = 0; d < SUP; d++)
            s = fmaf(z[(size_t)(p * SUP + d) * HID + t], ws[d * SUP + e], s);
        staO[(size_t)t * N_NODES + p * SUP + e] = s;
        zh[(size_t)(p * SUP + e) * HID + t] = s;
    }
}

__global__ void gemm_small(const float* __restrict__ zh,
                           const float* __restrict__ Wl,
                           const float* __restrict__ Wr,
                           float* __restrict__ G) {
    __shared__ float zr[HID];
    int i = blockIdx.x;
    int c = threadIdx.x;   // 256
    if (c < HID) zr[c] = zh[(size_t)i * HID + c];
    __syncthreads();
    const float* W = (c < GC) ? Wl : Wr;
    int cc = c & 127;
    float s = 0.f;
#pragma unroll
    for (int k = 0; k < HID; k++) s = fmaf(zr[k], W[k * GC + cc], s);
    G[(size_t)i * GC2 + c] = s;
}

// ---------------------------------------------------------------------------
extern "C" void kernel_launch(void* const* d_in, const int* in_sizes, int n_in,
                              void* d_out, int out_size) {
    const float* x    = (const float*)d_in[0];
    const float* Wl1  = (const float*)d_in[1];
    const float* Wr1  = (const float*)d_in[2];
    const float* a1   = (const float*)d_in[3];
    const float* Wm   = (const float*)d_in[4];
    const float* bm   = (const float*)d_in[5];
    const float* Wl2  = (const float*)d_in[6];
    const float* Wr2  = (const float*)d_in[7];
    const float* a2   = (const float*)d_in[8];
    const int*   adjS = (const int*)d_in[9];
    const int*   adjT = (const int*)d_in[10];

    float* out  = (float*)d_out;                           // [768,32]
    float* attS = out + N_NODES * HID;                     // [768,768,4]
    float* attT = attS + (size_t)N_NODES * N_NODES * NH;
    float* staO = attT + (size_t)N_NODES * N_NODES * NH;   // [32,768]

    float *gp, *g1, *g2, *z1, *zh, *es;
    __half *wh, *wlo;
    cudaGetSymbolAddress((void**)&gp, d_Gp);
    cudaGetSymbolAddress((void**)&g1, d_G1);
    cudaGetSymbolAddress((void**)&g2, d_G2);
    cudaGetSymbolAddress((void**)&z1, d_z1);
    cudaGetSymbolAddress((void**)&zh, d_zh);
    cudaGetSymbolAddress((void**)&es, d_es);
    cudaGetSymbolAddress((void**)&wh, d_Wh);
    cudaGetSymbolAddress((void**)&wlo, d_Wlo);

    const int SMEM_GEMM = (2 * 64 * ASTR * 2 + 2 * 32 * BSTR * 2) * 2;  // 88064
    cudaFuncSetAttribute(gemm_tc, cudaFuncAttributeMaxDynamicSharedMemorySize,
                         SMEM_GEMM);

    // layer 1
    split_w<<<(WAV * GC2 + 255) / 256, 256>>>(Wl1, Wr1, wh, wlo);
    gemm_tc<<<dim3(N_NODES / 64, GSPLITS), 256, SMEM_GEMM>>>(x, wh, wlo, gp);
    reduce_split<<<N_NODES * GC2 / 256, 256>>>(gp, g1);
    e_kernel<<<dim3(N_NODES / 32, N_NODES / 64), 256>>>(g1, adjS, a1, es);
    attw_kernel<<<N_NODES, 256>>>(es, attS);
    res_kernel<<<N_NODES / RT, 256>>>(g1, attS, z1, 1);

    // mapper
    mapper_kernel<<<P_PATCH, 256>>>(z1, Wm, bm, staO, zh);

    // layer 2
    gemm_small<<<N_NODES, 256>>>(zh, Wl2, Wr2, g2);
    e_kernel<<<dim3(N_NODES / 32, N_NODES / 64), 256>>>(g2, adjT, a2, es);
    attw_kernel<<<N_NODES, 256>>>(es, attT);
    res_kernel<<<N_NODES / RT, 256>>>(g2, attT, out, 0);
}